// round 4
// baseline (speedup 1.0000x reference)
#include <cuda_runtime.h>

#define HDIM 1024
#define WDIM 2048
#define GW (WDIM + 2)            // 2050
#define GH (HDIM + 2)            // 1026
#define GRID_CELLS (GH * GW)     // 2,103,300
#define MAXN 1048576
#define COUT 64
#define BN_EPS 1e-5f

// Scratch (static __device__ arrays: allocation-free per harness rules)
__device__ float g_grid[GRID_CELLS];     // padded dense grid, 8.4 MB
__device__ float g_s[9 * MAXN];          // gathered neighbor scalars, SoA [k][n], 36 MB
__device__ float g_m[9];                 // sum of s_k
__device__ float g_S[45];                // sum of s_j*s_k, upper triangular
__device__ float g_wp[9 * COUT];         // BN-folded weights
__device__ float g_bp[COUT];             // BN-folded bias

// ---------------------------------------------------------------------------
// K0: zero grid + stat accumulators (must be re-zeroed every launch)
// ---------------------------------------------------------------------------
__global__ void k_zero() {
    int i = blockIdx.x * blockDim.x + threadIdx.x;
    if (i < GRID_CELLS) g_grid[i] = 0.f;
    if (i < 9)  g_m[i] = 0.f;
    if (i < 45) g_S[i] = 0.f;
}

// ---------------------------------------------------------------------------
// K1: scatter active features into padded grid
// ---------------------------------------------------------------------------
__global__ void k_scatter(const float* __restrict__ feats,
                          const int* __restrict__ coords, int n) {
    int i = blockIdx.x * blockDim.x + threadIdx.x;
    if (i >= n) return;
    int y = coords[2 * i] + 1;
    int x = coords[2 * i + 1] + 1;
    g_grid[y * GW + x] = feats[i];
}

// ---------------------------------------------------------------------------
// K2: gather 9 neighbors per point, stash to SoA scratch, accumulate
//     first + second moments of the 9-vector (45 upper-tri products)
// ---------------------------------------------------------------------------
__global__ void __launch_bounds__(256)
k_gather_stats(const int* __restrict__ coords, int n) {
    int tid = blockIdx.x * blockDim.x + threadIdx.x;
    int stride = gridDim.x * blockDim.x;

    float m[9];
    float S[45];
#pragma unroll
    for (int j = 0; j < 9; j++) m[j] = 0.f;
#pragma unroll
    for (int j = 0; j < 45; j++) S[j] = 0.f;

    for (int i = tid; i < n; i += stride) {
        int y = coords[2 * i] + 1;
        int x = coords[2 * i + 1] + 1;
        int base = y * GW + x;
        float s[9];
#pragma unroll
        for (int dy = 0; dy < 3; dy++) {
            int b = base + (dy - 1) * GW;
            s[dy * 3 + 0] = __ldg(&g_grid[b - 1]);
            s[dy * 3 + 1] = __ldg(&g_grid[b]);
            s[dy * 3 + 2] = __ldg(&g_grid[b + 1]);
        }
        // coalesced SoA stash for the output pass
#pragma unroll
        for (int k = 0; k < 9; k++) g_s[k * MAXN + i] = s[k];
        // moments
        int idx = 0;
#pragma unroll
        for (int j = 0; j < 9; j++) {
            m[j] += s[j];
#pragma unroll
            for (int k = j; k < 9; k++) S[idx++] = fmaf(s[j], s[k], S[idx]);
        }
    }

    // warp tree-reduce all 54 partials
#pragma unroll
    for (int j = 0; j < 9; j++)
        for (int o = 16; o; o >>= 1) m[j] += __shfl_down_sync(0xffffffffu, m[j], o);
#pragma unroll
    for (int j = 0; j < 45; j++)
        for (int o = 16; o; o >>= 1) S[j] += __shfl_down_sync(0xffffffffu, S[j], o);

    __shared__ float sm[8 * 54];
    int lane = threadIdx.x & 31;
    int w = threadIdx.x >> 5;
    if (lane == 0) {
#pragma unroll
        for (int j = 0; j < 9; j++) sm[w * 54 + j] = m[j];
#pragma unroll
        for (int j = 0; j < 45; j++) sm[w * 54 + 9 + j] = S[j];
    }
    __syncthreads();
    int nw = blockDim.x >> 5;
    if (threadIdx.x < 54) {
        float acc = 0.f;
        for (int ww = 0; ww < nw; ww++) acc += sm[ww * 54 + threadIdx.x];
        if (threadIdx.x < 9) atomicAdd(&g_m[threadIdx.x], acc);
        else                 atomicAdd(&g_S[threadIdx.x - 9], acc);
    }
}

// ---------------------------------------------------------------------------
// K3: fold BN (batch stats via moment trick) into weights/bias.
//     mean_c = m̄·w_c ;  var_c = w_cᵀ(E[ssᵀ] − m̄m̄ᵀ)w_c
// ---------------------------------------------------------------------------
__global__ void k_finalize(const float* __restrict__ weight,
                           const float* __restrict__ gamma,
                           const float* __restrict__ beta, int n) {
    int c = threadIdx.x;
    if (c >= COUT) return;
    float inv_n = 1.f / (float)n;

    float mm[9], w[9];
#pragma unroll
    for (int j = 0; j < 9; j++) mm[j] = g_m[j] * inv_n;
#pragma unroll
    for (int k = 0; k < 9; k++) w[k] = weight[k * COUT + c];  // weight[k][0][c]

    float mean = 0.f;
#pragma unroll
    for (int k = 0; k < 9; k++) mean = fmaf(mm[k], w[k], mean);

    float e2 = 0.f;
    int idx = 0;
#pragma unroll
    for (int j = 0; j < 9; j++) {
#pragma unroll
        for (int k = j; k < 9; k++) {
            float Sjk = g_S[idx++] * inv_n;
            float coeff = (j == k) ? 1.f : 2.f;
            e2 = fmaf(coeff * Sjk, w[j] * w[k], e2);
        }
    }
    float var = fmaxf(e2 - mean * mean, 0.f);
    float scale = gamma[c] * rsqrtf(var + BN_EPS);
#pragma unroll
    for (int k = 0; k < 9; k++) g_wp[k * COUT + c] = w[k] * scale;
    g_bp[c] = fmaf(-mean, scale, beta[c]);
}

// ---------------------------------------------------------------------------
// K4: output pass. Warp handles one point per step; lane l covers channels
//     (2l, 2l+1) -> one coalesced 256B float2 row store per point.
//     s broadcast via shfl from a coalesced 32-point stage.
// ---------------------------------------------------------------------------
__global__ void __launch_bounds__(256)
k_out(float* __restrict__ out, int n) {
    int lane = threadIdx.x & 31;
    int gwarp = (blockIdx.x * blockDim.x + threadIdx.x) >> 5;
    int nwarps = (gridDim.x * blockDim.x) >> 5;
    int c0 = lane * 2;

    float2 wv[9];
#pragma unroll
    for (int k = 0; k < 9; k++)
        wv[k] = *(const float2*)(g_wp + k * COUT + c0);
    float2 bp = *(const float2*)(g_bp + c0);

    int nchunks = (n + 31) >> 5;
    for (int ch = gwarp; ch < nchunks; ch += nwarps) {
        int n0 = ch << 5;
        int i = n0 + lane;
        bool valid = i < n;
        float sl[9];
#pragma unroll
        for (int k = 0; k < 9; k++)
            sl[k] = valid ? g_s[k * MAXN + i] : 0.f;

        int pmax = min(32, n - n0);
#pragma unroll 4
        for (int p = 0; p < pmax; p++) {
            float2 acc = bp;
#pragma unroll
            for (int k = 0; k < 9; k++) {
                float sk = __shfl_sync(0xffffffffu, sl[k], p);
                acc.x = fmaf(sk, wv[k].x, acc.x);
                acc.y = fmaf(sk, wv[k].y, acc.y);
            }
            acc.x = fmaxf(acc.x, 0.f);
            acc.y = fmaxf(acc.y, 0.f);
            *(float2*)(out + (size_t)(n0 + p) * COUT + c0) = acc;
        }
    }
}

// ---------------------------------------------------------------------------
extern "C" void kernel_launch(void* const* d_in, const int* in_sizes, int n_in,
                              void* d_out, int out_size) {
    const float* feats  = (const float*)d_in[0];
    const float* weight = (const float*)d_in[1];  // [9][1][64]
    const float* gamma  = (const float*)d_in[2];
    const float* beta   = (const float*)d_in[3];
    const int*   coords = (const int*)d_in[4];    // [N][2]
    float* out = (float*)d_out;
    int n = in_sizes[0];  // N (C_IN == 1)

    k_zero<<<(GRID_CELLS + 255) / 256, 256>>>();
    k_scatter<<<(n + 255) / 256, 256>>>(feats, coords, n);
    k_gather_stats<<<1024, 256>>>(coords, n);
    k_finalize<<<1, 64>>>(weight, gamma, beta, n);
    k_out<<<1184, 256>>>(out, n);
}